// round 17
// baseline (speedup 1.0000x reference)
#include <cuda_runtime.h>
#include <cuda_bf16.h>
#include <cuda_fp16.h>
#include <cstdint>

// Problem constants
#define BATCH   4
#define S_LEN   1024
#define HID     1024
#define NHEADS  16
#define HDIM    64

typedef __nv_bfloat16 bf16;   // opaque 16-bit storage (holds fp16 bits here)

// ---------------------------------------------------------------------------
// Scratch (device globals: allocation-free per harness rules). All fp16 bits.
// ---------------------------------------------------------------------------
__device__ bf16 g_a16[BATCH * S_LEN * HID];     // aspect fp16
__device__ bf16 g_o16[BATCH * S_LEN * HID];     // opinion fp16
__device__ bf16 g_w16[4 * HID * HID];           // Wq(pre-scaled),Wk,Wv,Wo fp16
__device__ bf16 g_q16[BATCH * S_LEN * HID];     // q fp16 (pre-scaled), [b,h,s,d]
__device__ bf16 g_k16[BATCH * S_LEN * HID];     // k fp16
__device__ bf16 g_v16[BATCH * S_LEN * HID];     // v fp16
__device__ bf16 g_c16[BATCH * S_LEN * HID];     // ctx fp16, [b,s,h*d]

// ---------------------------------------------------------------------------
// sm_80-era PTX helpers (valid on base sm_100 target: NO tcgen05)
// ---------------------------------------------------------------------------
__device__ __forceinline__ uint32_t smem_u32(const void* p) {
    uint32_t a;
    asm("{ .reg .u64 t; cvta.to.shared.u64 t, %1; cvt.u32.u64 %0, t; }"
        : "=r"(a) : "l"(p));
    return a;
}
__device__ __forceinline__ void cp16(uint32_t dst, const void* src) {
    asm volatile("cp.async.cg.shared.global [%0], [%1], 16;"
                 :: "r"(dst), "l"(src));
}
__device__ __forceinline__ void ldsm_x4(uint32_t* r, uint32_t addr) {
    asm volatile("ldmatrix.sync.aligned.m8n8.x4.shared.b16 {%0,%1,%2,%3}, [%4];"
                 : "=r"(r[0]), "=r"(r[1]), "=r"(r[2]), "=r"(r[3]) : "r"(addr));
}
__device__ __forceinline__ void ldsm_x4_t(uint32_t* r, uint32_t addr) {
    asm volatile("ldmatrix.sync.aligned.m8n8.x4.trans.shared.b16 {%0,%1,%2,%3}, [%4];"
                 : "=r"(r[0]), "=r"(r[1]), "=r"(r[2]), "=r"(r[3]) : "r"(addr));
}
__device__ __forceinline__ void mma_f16(float* c, const uint32_t* a,
                                        uint32_t b0, uint32_t b1) {
    asm volatile(
        "mma.sync.aligned.m16n8k16.row.col.f32.f16.f16.f32 "
        "{%0,%1,%2,%3}, {%4,%5,%6,%7}, {%8,%9}, {%0,%1,%2,%3};"
        : "+f"(c[0]), "+f"(c[1]), "+f"(c[2]), "+f"(c[3])
        : "r"(a[0]), "r"(a[1]), "r"(a[2]), "r"(a[3]), "r"(b0), "r"(b1));
}
__device__ __forceinline__ uint32_t cvt_f16x2(float lo, float hi) {
    uint32_t r;
    asm("cvt.rn.f16x2.f32 %0, %1, %2;" : "=r"(r) : "f"(hi), "f"(lo));
    return r;
}

// ---------------------------------------------------------------------------
// One fused split kernel: blockIdx.y selects job.
//  y=0: aspect -> a16   y=1: opinion -> o16   y=2..5: Wq/Wk/Wv/Wo -> w16 slice
//  Wq (y==2) is pre-scaled by 0.125 = 1/sqrt(HDIM): folds the attention
//  scale into the Q projection (power-of-2 -> fp16 rounding commutes).
// ---------------------------------------------------------------------------
__global__ __launch_bounds__(256) void split_all_kernel(
    const float* __restrict__ aspect, const float* __restrict__ opinion,
    const float* __restrict__ w0, const float* __restrict__ w1,
    const float* __restrict__ w2, const float* __restrict__ w3,
    bf16* __restrict__ a16, bf16* __restrict__ o16,
    bf16* __restrict__ w16)
{
    const int y = blockIdx.y;
    const float* x;
    bf16* dst;
    int n4;
    float sc = 1.0f;
    if (y == 0)      { x = aspect;  dst = a16; n4 = BATCH * S_LEN * HID / 4; }
    else if (y == 1) { x = opinion; dst = o16; n4 = BATCH * S_LEN * HID / 4; }
    else {
        int w = y - 2;
        x = (w == 0) ? w0 : (w == 1) ? w1 : (w == 2) ? w2 : w3;
        dst = w16 + (size_t)w * HID * HID;
        n4 = HID * HID / 4;
        if (w == 0) sc = 0.125f;
    }
    int i = blockIdx.x * blockDim.x + threadIdx.x;
    int stride = gridDim.x * blockDim.x;
    for (; i < n4; i += stride) {
        float4 v = ((const float4*)x)[i];
        ((uint32_t*)dst)[2 * i]     = cvt_f16x2(v.x * sc, v.y * sc);
        ((uint32_t*)dst)[2 * i + 1] = cvt_f16x2(v.z * sc, v.w * sc);
    }
}

// ---------------------------------------------------------------------------
// Single-pass fp16 GEMM:  C = A_f16 @ W_f16^T + bias
// CTA tile 128x128, BK=64, 3-stage cp.async pipeline (32KB/stage, 96KB),
// 2 CTAs/SM (4 warps/SMSP), 8 warps (4M x 2N), warp tile 32x64.
// PERM=1: blockIdx.z selects Q/K/V; output single fp16 scatter to [b,h,s,d];
//         z==0 (Q) scales the bias by 0.125 (matches pre-scaled Wq).
// PERM=0: fp32 C out (O projection).
// ---------------------------------------------------------------------------
#define NKT 16                     // 1024 / 64
#define GSTG 32768                 // stage: A 16K | W 16K
#define GEMM_SMEM (3 * GSTG)       // 98304 bytes

template <int PERM>
__global__ __launch_bounds__(256, 2) void gemm_mma(
    const bf16* __restrict__ A0,   // fp16 bits (aspect / ctx)
    const bf16* __restrict__ A1,   // fp16 bits (opinion), for z=1,2
    const bf16* __restrict__ W16,
    const float* __restrict__ b0, const float* __restrict__ b1,
    const float* __restrict__ b2,
    float* __restrict__ C,
    bf16* __restrict__ O0, bf16* __restrict__ O1, bf16* __restrict__ O2)
{
    extern __shared__ __align__(128) bf16 gs[];

    const int z = blockIdx.z;
    const bf16* A = (z == 0) ? A0 : A1;
    const bf16* B = W16 + (size_t)z * HID * HID;
    const float* bias = (z == 0) ? b0 : (z == 1) ? b1 : b2;
    bf16* O = (z == 0) ? O0 : (z == 1) ? O1 : O2;
    const float bsc = (PERM == 1 && z == 0) ? 0.125f : 1.0f;

    const int tid = threadIdx.x;
    const int wid = tid >> 5;
    const int lid = tid & 31;
    const int m0 = blockIdx.y * 128;
    const int n0 = blockIdx.x * 128;
    const int mw = (wid & 3) * 32;      // 4 M-warps
    const int nw = (wid >> 2) * 64;     // 2 N-warps
    const uint32_t sb0 = smem_u32(gs);

    float acc[2][8][4];
#pragma unroll
    for (int mi = 0; mi < 2; mi++)
#pragma unroll
        for (int nj = 0; nj < 8; nj++)
#pragma unroll
            for (int e = 0; e < 4; e++) acc[mi][nj][e] = 0.f;

    auto load_stage = [&](int kt, int st) {
        const int kk = kt * 64;
        const uint32_t ab = sb0 + (uint32_t)st * (uint32_t)GSTG;
#pragma unroll
        for (int t = 0; t < 4; t++) {            // A: 1024 chunks
            int cq = tid + t * 256;
            int r = cq >> 3, c = cq & 7;
            uint32_t sw = (uint32_t)(r * 128 + ((c ^ (r & 7)) << 4));
            cp16(ab + sw,
                 (const char*)(A + (size_t)(m0 + r) * 1024 + kk) + c * 16);
        }
#pragma unroll
        for (int t = 0; t < 4; t++) {            // W: 1024 chunks
            int cq = tid + t * 256;
            int r = cq >> 3, c = cq & 7;
            uint32_t sw = (uint32_t)(r * 128 + ((c ^ (r & 7)) << 4));
            cp16(ab + 16384u + sw,
                 (const char*)(B + (size_t)(n0 + r) * 1024 + kk) + c * 16);
        }
        asm volatile("cp.async.commit_group;" ::: "memory");
    };

    load_stage(0, 0);
    load_stage(1, 1);

    const int grp = lid >> 3, rr = lid & 7;

    for (int kt = 0; kt < NKT; kt++) {
        if (kt + 1 < NKT)
            asm volatile("cp.async.wait_group 1;" ::: "memory");
        else
            asm volatile("cp.async.wait_group 0;" ::: "memory");
        __syncthreads();   // stage kt visible; all warps done with stage kt-1

        if (kt + 2 < NKT) load_stage(kt + 2, (kt + 2) % 3);

        const uint32_t ab = sb0 + (uint32_t)(kt % 3) * (uint32_t)GSTG;

#pragma unroll
        for (int ks = 0; ks < 4; ks++) {
            const int ch = ks * 2 + (grp >> 1);
            uint32_t af[2][4], bfr[4][4];
#pragma unroll
            for (int mi = 0; mi < 2; mi++) {
                int row = mw + mi * 16 + (grp & 1) * 8 + rr;
                ldsm_x4(af[mi], ab + (uint32_t)(row * 128 + ((ch ^ (row & 7)) << 4)));
            }
#pragma unroll
            for (int ni = 0; ni < 4; ni++) {
                int row = nw + ni * 16 + (grp & 1) * 8 + rr;
                ldsm_x4(bfr[ni], ab + 16384u +
                        (uint32_t)(row * 128 + ((ch ^ (row & 7)) << 4)));
            }
#pragma unroll
            for (int ni = 0; ni < 4; ni++)
#pragma unroll
                for (int mi = 0; mi < 2; mi++)
#pragma unroll
                    for (int od = 0; od < 2; od++)
                        mma_f16(acc[mi][2 * ni + od], af[mi],
                                bfr[ni][od], bfr[ni][2 + od]);
        }
    }

    // epilogue
    const int tq = lid >> 2, tr = lid & 3;
#pragma unroll
    for (int mi = 0; mi < 2; mi++) {
#pragma unroll
        for (int nj = 0; nj < 8; nj++) {
            int col  = n0 + nw + nj * 8 + tr * 2;
            float bb0 = bias[col] * bsc, bb1 = bias[col + 1] * bsc;
            int row0 = m0 + mw + mi * 16 + tq;
#pragma unroll
            for (int half = 0; half < 2; half++) {
                int row = row0 + half * 8;
                float v0 = acc[mi][nj][half * 2 + 0] + bb0;
                float v1 = acc[mi][nj][half * 2 + 1] + bb1;
                if (PERM == 0) {
                    *(float2*)&C[(size_t)row * 1024 + col] = make_float2(v0, v1);
                } else {
                    int b = row >> 10, s = row & 1023;
                    int h = col >> 6,  d = col & 63;
                    size_t idx = (((size_t)(b * NHEADS + h) << 10) + s) * HDIM + d;
                    *(uint32_t*)&O[idx] = cvt_f16x2(v0, v1);
                }
            }
        }
    }
}

// ---------------------------------------------------------------------------
// Tensorized flash attention, single-pass fp16 QK^T and PV.
// Q pre-scaled by 1/sqrt(d) (folded into Wq/bq) -> no per-score scale mul.
// O-rescale skipped (warp-uniform vote) when the running max is unchanged
// (multiply-by-1.0 elision: exact). 4 CTAs/SM.
// Span bias skipped: constant along softmax axis -> cancels exactly.
// ---------------------------------------------------------------------------
#define FLASH_SMEM 40960

__global__ __launch_bounds__(128, 4) void flash_mma(
    const int* __restrict__ mask,
    const bf16* __restrict__ q16, const bf16* __restrict__ k16,
    const bf16* __restrict__ v16, bf16* __restrict__ c16)
{
    extern __shared__ __align__(128) bf16 fs[];
    __shared__ int msk[S_LEN];

    const uint32_t base = smem_u32(fs);
    const int tid = threadIdx.x;
    const int wid = tid >> 5;
    const int lid = tid & 31;
    const int grp = lid >> 3, rr = lid & 7;
    const int qt = blockIdx.x;
    const int bh = blockIdx.y;
    const int b  = bh >> 4;
    const int h  = bh & 15;

    const size_t qoff = ((size_t)bh * S_LEN + qt * 64) * HDIM;
    const size_t koff = (size_t)bh * S_LEN * HDIM;

    for (int i = tid; i < S_LEN; i += 128) msk[i] = mask[b * S_LEN + i];

    auto load_kv = [&](int kt, int st) {
        const uint32_t sb = base + (uint32_t)st * 16384u;
#pragma unroll
        for (int i = 0; i < 4; i++) {
            int q = tid + i * 128;
            int r = q >> 3, c = q & 7;
            uint32_t sw = (uint32_t)(r * 128 + ((c ^ (r & 7)) << 4));
            const size_t g = koff + (size_t)(kt * 64 + r) * HDIM;
            cp16(sb + sw,         (const char*)(k16 + g) + c * 16);
            cp16(sb + 8192u + sw, (const char*)(v16 + g) + c * 16);
        }
        asm volatile("cp.async.commit_group;" ::: "memory");
    };

    // ---- prologue: stage Q through +32768; start K/V 0 ----
#pragma unroll
    for (int i = 0; i < 4; i++) {
        int q = tid + i * 128;
        int r = q >> 3, c = q & 7;
        uint32_t sw = (uint32_t)(r * 128 + ((c ^ (r & 7)) << 4));
        cp16(base + 32768u + sw, (const char*)(q16 + qoff + r * HDIM) + c * 16);
    }
    asm volatile("cp.async.commit_group;" ::: "memory");
    load_kv(0, 0);
    asm volatile("cp.async.wait_group 1;" ::: "memory");   // Q done
    __syncthreads();

    uint32_t qf[4][4];
    {
        int row = wid * 16 + (grp & 1) * 8 + rr;
#pragma unroll
        for (int t = 0; t < 4; t++) {
            int ch = t * 2 + (grp >> 1);
            ldsm_x4(qf[t], base + 32768u +
                (uint32_t)(row * 128 + ((ch ^ (row & 7)) << 4)));
        }
    }

    float o[8][4];
#pragma unroll
    for (int n8 = 0; n8 < 8; n8++)
#pragma unroll
        for (int e = 0; e < 4; e++) o[n8][e] = 0.f;
    float m0 = -1e30f, m1 = -1e30f, l0 = 0.f, l1 = 0.f;

    for (int kt = 0; kt < 16; kt++) {
        asm volatile("cp.async.wait_group 0;" ::: "memory");  // stage kt done
        __syncthreads();
        if (kt + 1 < 16) load_kv(kt + 1, (kt + 1) & 1);       // overlaps compute

        const uint32_t sb = base + (uint32_t)(kt & 1) * 16384u;

        // ---- S = Q K^T (single-pass fp16; Q pre-scaled) ----
        float s[8][4];
#pragma unroll
        for (int n8 = 0; n8 < 8; n8++)
#pragma unroll
            for (int e = 0; e < 4; e++) s[n8][e] = 0.f;

#pragma unroll
        for (int t = 0; t < 4; t++) {
            int ch = t * 2 + (grp >> 1);
            uint32_t kf[4][4];
#pragma unroll
            for (int ni = 0; ni < 4; ni++) {
                int row = ni * 16 + (grp & 1) * 8 + rr;
                ldsm_x4(kf[ni], sb + (uint32_t)(row * 128 + ((ch ^ (row & 7)) << 4)));
            }
#pragma unroll
            for (int ni = 0; ni < 4; ni++) {
                mma_f16(s[2 * ni],     qf[t], kf[ni][0], kf[ni][2]);
                mma_f16(s[2 * ni + 1], qf[t], kf[ni][1], kf[ni][3]);
            }
        }

        // ---- mask (scale already folded into Q) ----
#pragma unroll
        for (int n8 = 0; n8 < 8; n8++) {
            int col = kt * 64 + n8 * 8 + (lid & 3) * 2;
            int mv0 = msk[col], mv1 = msk[col + 1];
            if (!mv0) { s[n8][0] = -1e30f; s[n8][2] = -1e30f; }
            if (!mv1) { s[n8][1] = -1e30f; s[n8][3] = -1e30f; }
        }

        // ---- online softmax ----
        float mt0 = -1e30f, mt1 = -1e30f;
#pragma unroll
        for (int n8 = 0; n8 < 8; n8++) {
            mt0 = fmaxf(mt0, fmaxf(s[n8][0], s[n8][1]));
            mt1 = fmaxf(mt1, fmaxf(s[n8][2], s[n8][3]));
        }
        mt0 = fmaxf(mt0, __shfl_xor_sync(0xffffffffu, mt0, 1));
        mt0 = fmaxf(mt0, __shfl_xor_sync(0xffffffffu, mt0, 2));
        mt1 = fmaxf(mt1, __shfl_xor_sync(0xffffffffu, mt1, 1));
        mt1 = fmaxf(mt1, __shfl_xor_sync(0xffffffffu, mt1, 2));
        float mn0 = fmaxf(m0, mt0), mn1 = fmaxf(m1, mt1);
        float cr0 = __expf(m0 - mn0), cr1 = __expf(m1 - mn1);
        m0 = mn0; m1 = mn1;
        float ps0 = 0.f, ps1 = 0.f;
#pragma unroll
        for (int n8 = 0; n8 < 8; n8++) {
            s[n8][0] = __expf(s[n8][0] - mn0);
            s[n8][1] = __expf(s[n8][1] - mn0);
            s[n8][2] = __expf(s[n8][2] - mn1);
            s[n8][3] = __expf(s[n8][3] - mn1);
            ps0 += s[n8][0] + s[n8][1];
            ps1 += s[n8][2] + s[n8][3];
        }
        ps0 += __shfl_xor_sync(0xffffffffu, ps0, 1);
        ps0 += __shfl_xor_sync(0xffffffffu, ps0, 2);
        ps1 += __shfl_xor_sync(0xffffffffu, ps1, 1);
        ps1 += __shfl_xor_sync(0xffffffffu, ps1, 2);
        l0 = l0 * cr0 + ps0;
        l1 = l1 * cr1 + ps1;
        // rescale only when the running max moved (skip x1.0 muls: exact)
        if (__any_sync(0xffffffffu, (cr0 != 1.0f) || (cr1 != 1.0f))) {
#pragma unroll
            for (int n8 = 0; n8 < 8; n8++) {
                o[n8][0] *= cr0; o[n8][1] *= cr0;
                o[n8][2] *= cr1; o[n8][3] *= cr1;
            }
        }

        // ---- P -> fp16 A-fragments ----
        uint32_t ph[4][4];
#pragma unroll
        for (int t = 0; t < 4; t++) {
            ph[t][0] = cvt_f16x2(s[2 * t][0], s[2 * t][1]);
            ph[t][1] = cvt_f16x2(s[2 * t][2], s[2 * t][3]);
            ph[t][2] = cvt_f16x2(s[2 * t + 1][0], s[2 * t + 1][1]);
            ph[t][3] = cvt_f16x2(s[2 * t + 1][2], s[2 * t + 1][3]);
        }

        // ---- O += P V (single-pass fp16; 4 LDSM batched per t) ----
#pragma unroll
        for (int t = 0; t < 4; t++) {
            int row = t * 16 + (grp & 1) * 8 + rr;
            uint32_t vf[4][4];
#pragma unroll
            for (int g = 0; g < 4; g++) {
                int ch = g * 2 + (grp >> 1);
                ldsm_x4_t(vf[g], sb + 8192u +
                    (uint32_t)(row * 128 + ((ch ^ (row & 7)) << 4)));
            }
#pragma unroll
            for (int g = 0; g < 4; g++) {
                mma_f16(o[2 * g],     ph[t], vf[g][0], vf[g][1]);
                mma_f16(o[2 * g + 1], ph[t], vf[g][2], vf[g][3]);
            }
        }
    }

    // ---- normalize + write ctx as single fp16, [b,s,h*64+d] ----
    const float inv0 = 1.0f / l0, inv1 = 1.0f / l1;
    const int row0 = qt * 64 + wid * 16 + (lid >> 2);
#pragma unroll
    for (int n8 = 0; n8 < 8; n8++) {
        int col = n8 * 8 + (lid & 3) * 2;
        size_t i0 = ((size_t)(b * S_LEN + row0)) * HID + h * HDIM + col;
        *(uint32_t*)&c16[i0] = cvt_f16x2(o[n8][0] * inv0, o[n8][1] * inv0);
        size_t i1 = ((size_t)(b * S_LEN + row0 + 8)) * HID + h * HDIM + col;
        *(uint32_t*)&c16[i1] = cvt_f16x2(o[n8][2] * inv1, o[n8][3] * inv1);
    }
}

// ---------------------------------------------------------------------------
extern "C" void kernel_launch(void* const* d_in, const int* in_sizes, int n_in,
                              void* d_out, int out_size)
{
    const float* aspect  = (const float*)d_in[0];
    const float* opinion = (const float*)d_in[1];
    const int*   mask    = (const int*)  d_in[2];
    const float* Wq = (const float*)d_in[3];
    const float* bq = (const float*)d_in[4];
    const float* Wk = (const float*)d_in[5];
    const float* bk = (const float*)d_in[6];
    const float* Wv = (const float*)d_in[7];
    const float* bv = (const float*)d_in[8];
    const float* Wo = (const float*)d_in[9];
    const float* bo = (const float*)d_in[10];
    // d_in[11]/d_in[12] (Wbil/bbil): span bias is constant along the softmax
    // axis -> cancels exactly (shift invariance). Intentionally unused.
    float* out = (float*)d_out;

    bf16 *a16, *o16, *w16, *q16, *k16, *v16, *c16;
    cudaGetSymbolAddress((void**)&a16, g_a16);
    cudaGetSymbolAddress((void**)&o16, g_o16);
    cudaGetSymbolAddress((void**)&w16, g_w16);
    cudaGetSymbolAddress((void**)&q16, g_q16);
    cudaGetSymbolAddress((void**)&k16, g_k16);
    cudaGetSymbolAddress((void**)&v16, g_v16);
    cudaGetSymbolAddress((void**)&c16, g_c16);

    cudaFuncSetAttribute(gemm_mma<0>,
        cudaFuncAttributeMaxDynamicSharedMemorySize, GEMM_SMEM);
    cudaFuncSetAttribute(gemm_mma<1>,
        cudaFuncAttributeMaxDynamicSharedMemorySize, GEMM_SMEM);
    cudaFuncSetAttribute(flash_mma,
        cudaFuncAttributeMaxDynamicSharedMemorySize, FLASH_SMEM);

    // one fused split launch (aspect, opinion, 4 weight matrices)
    split_all_kernel<<<dim3(192, 6), 256>>>(
        aspect, opinion, Wq, Wk, Wv, Wo, a16, o16, w16);

    // fused Q/K/V projections: grid.z selects; CTA tile 128x128, 2 CTAs/SM
    gemm_mma<1><<<dim3(8, 32, 3), 256, GEMM_SMEM>>>(
        a16, o16, w16, bq, bk, bv, nullptr, q16, k16, v16);

    flash_mma<<<dim3(16, 64), 128, FLASH_SMEM>>>(mask, q16, k16, v16, c16);

    // O projection: A = ctx fp16, weight slice 3, fp32 out
    gemm_mma<0><<<dim3(8, 32, 1), 256, GEMM_SMEM>>>(
        c16, nullptr, w16 + 3 * (size_t)HID * HID,
        bo, nullptr, nullptr, out, nullptr, nullptr, nullptr);
}